// round 1
// baseline (speedup 1.0000x reference)
#include <cuda_runtime.h>
#include <math.h>

// Problem constants (fixed by the dataset)
#define NNODES 200000
#define HSZ    256
#define XSZ    256
#define KK     512          // packed K = XSZ + HSZ
#define NOUT   1024         // packed output cols = 768 (iou) + 256 (f), interleaved as quads
#define NE     200000

// -------- device scratch (static allocation is the sanctioned workaround) -----
__device__ float g_hsum[NNODES * HSZ];   // 200 MB
__device__ float g_csum[NNODES * HSZ];   // 200 MB
__device__ float g_Wp[KK * NOUT];        // 2 MB packed weights, col = 4*q + t, t in {i,o,u,f}
__device__ float g_bias[NOUT];

// ---------------------------------------------------------------------------
// Kernel 0: zero the accumulators (graph replay must start from zeros)
// ---------------------------------------------------------------------------
__global__ void zero_kernel() {
    long long idx = (long long)blockIdx.x * blockDim.x + threadIdx.x;
    long long total4 = (long long)NNODES * HSZ / 4;   // float4 count per array
    float4 z = make_float4(0.f, 0.f, 0.f, 0.f);
    for (long long i = idx; i < total4; i += (long long)gridDim.x * blockDim.x) {
        ((float4*)g_hsum)[i] = z;
        ((float4*)g_csum)[i] = z;
    }
}

// ---------------------------------------------------------------------------
// Kernel 1: pack weights into interleaved-gate layout.
//   Wp[k][4q+t]: t=0: i-row q, t=1: o-row 256+q, t=2: u-row 512+q, t=3: f-row q
//   k < 256  -> x-side weights (W_iou; f side is zero)
//   k >= 256 -> h_sum-side weights (U_iou; U_f_w for t=3)
// ---------------------------------------------------------------------------
__global__ void pack_kernel(const float* __restrict__ Wiou,
                            const float* __restrict__ Uiou,
                            const float* __restrict__ biou,
                            const float* __restrict__ Ufw,
                            const float* __restrict__ Ufb) {
    int idx = blockIdx.x * blockDim.x + threadIdx.x;
    if (idx < KK * NOUT) {
        int k = idx >> 10;          // 0..511
        int col = idx & (NOUT - 1); // 0..1023
        int q = col >> 2;
        int t = col & 3;
        float v;
        if (k < 256) {
            v = (t < 3) ? Wiou[(t * 256 + q) * XSZ + k] : 0.0f;
        } else {
            int kk = k - 256;
            v = (t < 3) ? Uiou[(t * 256 + q) * HSZ + kk] : Ufw[q * HSZ + kk];
        }
        g_Wp[idx] = v;
    }
    if (idx < NOUT) {
        int q = idx >> 2;
        int t = idx & 3;
        g_bias[idx] = (t < 3) ? biou[t * 256 + q] : Ufb[q];
    }
}

// ---------------------------------------------------------------------------
// Kernel 2: edge scatter-add.  4 edges per 256-thread block, 64 threads/edge,
// float4 loads + 4 scalar atomicAdds each for h and c.
// ---------------------------------------------------------------------------
__global__ void scatter_kernel(const float* __restrict__ h,
                               const float* __restrict__ c,
                               const int* __restrict__ src,
                               const int* __restrict__ dst,
                               int E) {
    int e = blockIdx.x * 4 + (threadIdx.x >> 6);
    if (e >= E) return;
    int lane = threadIdx.x & 63;
    int s = src[e];
    int d = dst[e];
    int off = lane * 4;
    float4 hv = *(const float4*)&h[(long long)s * HSZ + off];
    float4 cv = *(const float4*)&c[(long long)s * HSZ + off];
    float* hp = &g_hsum[(long long)d * HSZ + off];
    float* cp = &g_csum[(long long)d * HSZ + off];
    atomicAdd(hp + 0, hv.x); atomicAdd(hp + 1, hv.y);
    atomicAdd(hp + 2, hv.z); atomicAdd(hp + 3, hv.w);
    atomicAdd(cp + 0, cv.x); atomicAdd(cp + 1, cv.y);
    atomicAdd(cp + 2, cv.z); atomicAdd(cp + 3, cv.w);
}

// ---------------------------------------------------------------------------
// Kernel 3: fused GEMM + TreeLSTM epilogue.
//   G[n, 4q+t] = sum_k A[n,k] * Wp[k, 4q+t] + bias,   A = [x | h_sum]
//   then per (n, q): c_new = sig(i)*tanh(u) + sig(f)*c_sum ; h_new = sig(o)*tanh(c_new)
// Classic 128x128x16 SGEMM, 256 threads, 8x8 micro-tile.
// ---------------------------------------------------------------------------
#define BM 128
#define BN 128
#define BKt 16

__device__ __forceinline__ float sigmoidf_(float v) {
    return 1.0f / (1.0f + expf(-v));
}

__global__ void __launch_bounds__(256, 2)
gemm_epilogue_kernel(const float* __restrict__ x,
                     float* __restrict__ hout,
                     float* __restrict__ cout,
                     int M) {
    __shared__ float As[BKt][BM];
    __shared__ float Bs[BKt][BN];

    const int tid = threadIdx.x;
    const int ty = tid >> 4;     // 0..15 -> row group
    const int tx = tid & 15;     // 0..15 -> col group
    const int m0 = blockIdx.y * BM;
    const int n0 = blockIdx.x * BN;

    float acc[8][8];
#pragma unroll
    for (int i = 0; i < 8; i++)
#pragma unroll
        for (int j = 0; j < 8; j++) acc[i][j] = 0.0f;

    for (int k0 = 0; k0 < KK; k0 += BKt) {
        const float* A = (k0 < 256) ? x : g_hsum;
        const int ka = (k0 < 256) ? k0 : (k0 - 256);

        // ---- load A tile (transposed into As[k][m]) : 512 float4, 2/thread
#pragma unroll
        for (int l = tid; l < 512; l += 256) {
            int row = l >> 2;             // 0..127
            int kq = (l & 3) * 4;         // 0,4,8,12
            int gr = m0 + row;
            float4 v;
            if (gr < M) v = *(const float4*)&A[(long long)gr * 256 + ka + kq];
            else        v = make_float4(0.f, 0.f, 0.f, 0.f);
            As[kq + 0][row] = v.x;
            As[kq + 1][row] = v.y;
            As[kq + 2][row] = v.z;
            As[kq + 3][row] = v.w;
        }
        // ---- load B tile : 512 float4, 2/thread, direct
#pragma unroll
        for (int l = tid; l < 512; l += 256) {
            int kk = l >> 5;              // 0..15
            int c4 = (l & 31) * 4;        // 0..124
            *(float4*)&Bs[kk][c4] =
                *(const float4*)&g_Wp[(long long)(k0 + kk) * NOUT + n0 + c4];
        }
        __syncthreads();

#pragma unroll
        for (int k = 0; k < BKt; k++) {
            float ra[8], rb[8];
            *(float4*)&ra[0] = *(const float4*)&As[k][ty * 8 + 0];
            *(float4*)&ra[4] = *(const float4*)&As[k][ty * 8 + 4];
            *(float4*)&rb[0] = *(const float4*)&Bs[k][tx * 8 + 0];
            *(float4*)&rb[4] = *(const float4*)&Bs[k][tx * 8 + 4];
#pragma unroll
            for (int i = 0; i < 8; i++)
#pragma unroll
                for (int j = 0; j < 8; j++)
                    acc[i][j] = fmaf(ra[i], rb[j], acc[i][j]);
        }
        __syncthreads();
    }

    // ---- fused TreeLSTM epilogue -----------------------------------------
    // thread columns n0+tx*8+{0..7} = two complete gate quadruples
    const int colbase = n0 + tx * 8;
#pragma unroll
    for (int i = 0; i < 8; i++) {
        int n = m0 + ty * 8 + i;
        if (n >= M) continue;
#pragma unroll
        for (int p = 0; p < 2; p++) {
            int q = (colbase >> 2) + p;     // global hidden index 0..255
            float zi = acc[i][p * 4 + 0] + g_bias[4 * q + 0];
            float zo = acc[i][p * 4 + 1] + g_bias[4 * q + 1];
            float zu = acc[i][p * 4 + 2] + g_bias[4 * q + 2];
            float zf = acc[i][p * 4 + 3] + g_bias[4 * q + 3];
            float cs = g_csum[(long long)n * HSZ + q];
            float cn = sigmoidf_(zi) * tanhf(zu) + sigmoidf_(zf) * cs;
            float hn = sigmoidf_(zo) * tanhf(cn);
            hout[(long long)n * HSZ + q] = hn;
            cout[(long long)n * HSZ + q] = cn;
        }
    }
}

// ---------------------------------------------------------------------------
// launch
// ---------------------------------------------------------------------------
extern "C" void kernel_launch(void* const* d_in, const int* in_sizes, int n_in,
                              void* d_out, int out_size) {
    const float* x    = (const float*)d_in[0];
    // d_in[1] = h, d_in[2] = c
    const float* h    = (const float*)d_in[1];
    const float* c    = (const float*)d_in[2];
    const int*   src  = (const int*)d_in[3];
    const int*   dst  = (const int*)d_in[4];
    const float* Wiou = (const float*)d_in[5];
    const float* Uiou = (const float*)d_in[6];
    const float* biou = (const float*)d_in[7];
    const float* Ufw  = (const float*)d_in[8];
    const float* Ufb  = (const float*)d_in[9];

    const int E = in_sizes[3];
    const int M = in_sizes[0] / XSZ;   // 200000

    float* hout = (float*)d_out;
    float* cout = (float*)d_out + (long long)M * HSZ;

    // 0) zero accumulators
    zero_kernel<<<4096, 256>>>();

    // 1) pack weights
    pack_kernel<<<(KK * NOUT + 255) / 256, 256>>>(Wiou, Uiou, biou, Ufw, Ufb);

    // 2) scatter-add child states
    scatter_kernel<<<(E + 3) / 4, 256>>>(h, c, src, dst, E);

    // 3) fused GEMM + epilogue
    dim3 grid(NOUT / BN, (M + BM - 1) / BM);
    gemm_epilogue_kernel<<<grid, 256>>>(x, hout, cout, M);
}

// round 3
// speedup vs baseline: 1.7808x; 1.7808x over previous
#include <cuda_runtime.h>
#include <cuda_bf16.h>
#include <math.h>
#include <stdint.h>

// Problem constants (fixed by the dataset)
#define NNODES 200000
#define HSZ    256
#define XSZ    256
#define KK     512          // packed K = XSZ + HSZ
#define NOUT   1024         // packed cols, interleaved gate quads (i,o,u,f)

// ---------------- device scratch (static allocation) ------------------------
__device__ float g_hsum[NNODES * HSZ];                 // 200 MB
__device__ float g_csum[NNODES * HSZ];                 // 200 MB
__device__ __nv_bfloat16 g_Ah[(size_t)NNODES * KK];    // 204.8 MB
__device__ __nv_bfloat16 g_Al[(size_t)NNODES * KK];    // 204.8 MB
__device__ __nv_bfloat16 g_Bh[NOUT * KK];              // 1 MB  [n][k] K-major
__device__ __nv_bfloat16 g_Bl[NOUT * KK];              // 1 MB
__device__ float g_bias[NOUT];

// ---------------- PTX helpers (all baseline compute_103, no 'a' features) ---
__device__ __forceinline__ uint32_t s2u(const void* p) {
    uint32_t a;
    asm("{ .reg .u64 t; cvta.to.shared.u64 t, %1; cvt.u32.u64 %0, t; }"
        : "=r"(a) : "l"(p));
    return a;
}
#define CPA16(dst, src) \
    asm volatile("cp.async.cg.shared.global [%0], [%1], 16;" :: "r"(dst), "l"(src) : "memory")
#define CPA_COMMIT() asm volatile("cp.async.commit_group;" ::: "memory")

__device__ __forceinline__ void ldsm4(uint32_t* r, uint32_t addr) {
    asm volatile("ldmatrix.sync.aligned.m8n8.x4.shared.b16 {%0,%1,%2,%3}, [%4];"
                 : "=r"(r[0]), "=r"(r[1]), "=r"(r[2]), "=r"(r[3]) : "r"(addr));
}
__device__ __forceinline__ void mma16816(float* d, const uint32_t* a, const uint32_t* b) {
    asm volatile("mma.sync.aligned.m16n8k16.row.col.f32.bf16.bf16.f32 "
                 "{%0,%1,%2,%3}, {%4,%5,%6,%7}, {%8,%9}, {%0,%1,%2,%3};"
                 : "+f"(d[0]), "+f"(d[1]), "+f"(d[2]), "+f"(d[3])
                 : "r"(a[0]), "r"(a[1]), "r"(a[2]), "r"(a[3]), "r"(b[0]), "r"(b[1]));
}

// fast sigmoid/tanh via ex2/rcp approx (rel err ~1e-6)
__device__ __forceinline__ float fexp2_(float x) {
    float y; asm("ex2.approx.ftz.f32 %0, %1;" : "=f"(y) : "f"(x)); return y;
}
__device__ __forceinline__ float frcp_(float x) {
    float y; asm("rcp.approx.ftz.f32 %0, %1;" : "=f"(y) : "f"(x)); return y;
}
__device__ __forceinline__ float sig_(float x) {
    return frcp_(1.0f + fexp2_(-1.4426950408889634f * x));
}
__device__ __forceinline__ float tanh_(float x) {
    return 2.0f * frcp_(1.0f + fexp2_(-2.8853900817779268f * x)) - 1.0f;
}

// ---------------------------------------------------------------------------
// Kernel 0: zero accumulators
// ---------------------------------------------------------------------------
__global__ void zero_kernel() {
    long long idx = (long long)blockIdx.x * blockDim.x + threadIdx.x;
    long long total4 = (long long)NNODES * HSZ / 4;
    float4 z = make_float4(0.f, 0.f, 0.f, 0.f);
    for (long long i = idx; i < total4; i += (long long)gridDim.x * blockDim.x) {
        ((float4*)g_hsum)[i] = z;
        ((float4*)g_csum)[i] = z;
    }
}

// ---------------------------------------------------------------------------
// Kernel 1: pack weights -> bf16 hi/lo, layout [n][k] K-major, n = 4q+t
// ---------------------------------------------------------------------------
__global__ void pack_kernel(const float* __restrict__ Wiou,
                            const float* __restrict__ Uiou,
                            const float* __restrict__ biou,
                            const float* __restrict__ Ufw,
                            const float* __restrict__ Ufb) {
    int idx = blockIdx.x * blockDim.x + threadIdx.x;
    if (idx < NOUT * KK) {
        int n = idx >> 9;
        int k = idx & (KK - 1);
        int q = n >> 2;
        int t = n & 3;
        float v;
        if (k < 256) {
            v = (t < 3) ? Wiou[(t * 256 + q) * XSZ + k] : 0.0f;
        } else {
            int kk = k - 256;
            v = (t < 3) ? Uiou[(t * 256 + q) * HSZ + kk] : Ufw[q * HSZ + kk];
        }
        __nv_bfloat16 hi = __float2bfloat16(v);
        __nv_bfloat16 lo = __float2bfloat16(v - __bfloat162float(hi));
        g_Bh[idx] = hi;
        g_Bl[idx] = lo;
    }
    if (idx < NOUT) {
        int q = idx >> 2;
        int t = idx & 3;
        g_bias[idx] = (t < 3) ? biou[t * 256 + q] : Ufb[q];
    }
}

// ---------------------------------------------------------------------------
// Kernel 2: edge scatter-add
// ---------------------------------------------------------------------------
__global__ void scatter_kernel(const float* __restrict__ h,
                               const float* __restrict__ c,
                               const int* __restrict__ src,
                               const int* __restrict__ dst,
                               int E) {
    int e = blockIdx.x * 4 + (threadIdx.x >> 6);
    if (e >= E) return;
    int lane = threadIdx.x & 63;
    int s = src[e];
    int d = dst[e];
    int off = lane * 4;
    float4 hv = *(const float4*)&h[(long long)s * HSZ + off];
    float4 cv = *(const float4*)&c[(long long)s * HSZ + off];
    float* hp = &g_hsum[(long long)d * HSZ + off];
    float* cp = &g_csum[(long long)d * HSZ + off];
    atomicAdd(hp + 0, hv.x); atomicAdd(hp + 1, hv.y);
    atomicAdd(hp + 2, hv.z); atomicAdd(hp + 3, hv.w);
    atomicAdd(cp + 0, cv.x); atomicAdd(cp + 1, cv.y);
    atomicAdd(cp + 2, cv.z); atomicAdd(cp + 3, cv.w);
}

// ---------------------------------------------------------------------------
// Kernel 3: convert A = [x | hsum] -> bf16 hi/lo [m][512]
// ---------------------------------------------------------------------------
__global__ void convert_kernel(const float* __restrict__ x, int M) {
    long long i = (long long)blockIdx.x * blockDim.x + threadIdx.x;
    long long total = (long long)M * 128;          // one float4 each
    if (i >= total) return;
    int m = (int)(i >> 7);
    int k = ((int)i & 127) * 4;
    const float* sp = (k < 256) ? &x[(long long)m * 256 + k]
                                : &g_hsum[(long long)m * 256 + (k - 256)];
    float4 v = *(const float4*)sp;
    float vv[4] = {v.x, v.y, v.z, v.w};
    __nv_bfloat16 hi[4], lo[4];
#pragma unroll
    for (int j = 0; j < 4; j++) {
        hi[j] = __float2bfloat16(vv[j]);
        lo[j] = __float2bfloat16(vv[j] - __bfloat162float(hi[j]));
    }
    long long off = (long long)m * KK + k;
    *(__nv_bfloat162*)&g_Ah[off + 0] = __nv_bfloat162{hi[0], hi[1]};
    *(__nv_bfloat162*)&g_Ah[off + 2] = __nv_bfloat162{hi[2], hi[3]};
    *(__nv_bfloat162*)&g_Al[off + 0] = __nv_bfloat162{lo[0], lo[1]};
    *(__nv_bfloat162*)&g_Al[off + 2] = __nv_bfloat162{lo[2], lo[3]};
}

// ---------------------------------------------------------------------------
// Kernel 4: bf16 mma.sync GEMM (128x128xK512, hi/lo 3-pass) + fused epilogue
//   smem stage: Ah/Al/Bh/Bl tiles, 128 rows x 32 bf16, padded row = 80 B
// ---------------------------------------------------------------------------
#define BK        32
#define ROWB      80                       // padded row bytes (40 bf16)
#define SEC_B     (128 * ROWB)             // 10240 B per matrix section
#define STAGE_B   (4 * SEC_B)              // 40960 B
#define NSTG      3
#define KITERS    (KK / BK)                // 16
#define DYN_SMEM  (NSTG * STAGE_B)         // 122880 B

__global__ void __launch_bounds__(256, 1)
gemm_mma_kernel(float* __restrict__ hout, float* __restrict__ cout, int M) {
    extern __shared__ __align__(128) char sm[];
    __shared__ float s_bias[128];

    const int tid  = threadIdx.x;
    const int lane = tid & 31;
    const int wid  = tid >> 5;
    const int wm   = wid >> 2;            // 0..1  (64-row band)
    const int wn   = wid & 3;             // 0..3  (32-col band)
    const int m0   = blockIdx.y * 128;
    const int n0   = blockIdx.x * 128;
    const uint32_t smb = s2u(sm);

    if (tid < 128) s_bias[tid] = g_bias[n0 + tid];

    // ---- stage loader: 2048 x 16B cp.async ---------------------------------
    auto load_stage = [&](int s) {
        const uint32_t base = smb + (s % NSTG) * STAGE_B;
        const int k0 = s * BK;
#pragma unroll
        for (int i = 0; i < 8; i++) {
            int l = tid + i * 256;
            int sec = l >> 9;             // 0=Ah 1=Al 2=Bh 3=Bl
            int w = l & 511;
            int row = w >> 2;
            int ch = w & 3;
            const __nv_bfloat16* src;
            if (sec < 2) {
                int gr = m0 + row; if (gr >= M) gr = M - 1;
                const __nv_bfloat16* g = sec ? g_Al : g_Ah;
                src = g + (long long)gr * KK + k0 + ch * 8;
            } else {
                const __nv_bfloat16* g = (sec == 3) ? g_Bl : g_Bh;
                src = g + (long long)(n0 + row) * KK + k0 + ch * 8;
            }
            uint32_t dst = base + sec * SEC_B + row * ROWB + ch * 16;
            CPA16(dst, src);
        }
        CPA_COMMIT();
    };

    load_stage(0);
    load_stage(1);
    load_stage(2);

    float acc[4][4][4];
#pragma unroll
    for (int i = 0; i < 4; i++)
#pragma unroll
        for (int j = 0; j < 4; j++)
#pragma unroll
            for (int p = 0; p < 4; p++) acc[i][j][p] = 0.0f;

    for (int s = 0; s < KITERS; s++) {
        if (s <= KITERS - 3)      asm volatile("cp.async.wait_group 2;" ::: "memory");
        else if (s == KITERS - 2) asm volatile("cp.async.wait_group 1;" ::: "memory");
        else                      asm volatile("cp.async.wait_group 0;" ::: "memory");
        __syncthreads();

        const uint32_t base = smb + (s % NSTG) * STAGE_B;
        const uint32_t aRow = (wm * 64 + (lane & 15)) * ROWB + (lane >> 4) * 16;
        const uint32_t bRow = (wn * 32 + (lane & 7) + ((lane >> 4) & 1) * 8) * ROWB
                              + ((lane >> 3) & 1) * 16;

#pragma unroll
        for (int t = 0; t < 2; t++) {
            const uint32_t kb = t * 32;
            uint32_t ah[4][4], al[4][4], bh[2][4], bl[2][4];
#pragma unroll
            for (int i = 0; i < 4; i++) {
                ldsm4(ah[i], base + 0 * SEC_B + aRow + i * 16 * ROWB + kb);
                ldsm4(al[i], base + 1 * SEC_B + aRow + i * 16 * ROWB + kb);
            }
#pragma unroll
            for (int j = 0; j < 2; j++) {
                ldsm4(bh[j], base + 2 * SEC_B + bRow + j * 16 * ROWB + kb);
                ldsm4(bl[j], base + 3 * SEC_B + bRow + j * 16 * ROWB + kb);
            }
#pragma unroll
            for (int i = 0; i < 4; i++) {
#pragma unroll
                for (int jt = 0; jt < 4; jt++) {
                    const uint32_t* bp_h = &bh[jt >> 1][(jt & 1) * 2];
                    const uint32_t* bp_l = &bl[jt >> 1][(jt & 1) * 2];
                    mma16816(acc[i][jt], ah[i], bp_h);
                    mma16816(acc[i][jt], ah[i], bp_l);
                    mma16816(acc[i][jt], al[i], bp_h);
                }
            }
        }
        __syncthreads();
        if (s + NSTG < KITERS) load_stage(s + NSTG);
    }

    // ---- fused TreeLSTM epilogue ------------------------------------------
    // cols for this thread: c0 = wn*32 + j*8 + (lane&3)*2 -> gate t = {0,1} or {2,3}
    // pair lanes (l, l^1) reassemble one full (i,o,u,f) quad.
    const int mbase = m0 + wm * 64;
    const int qbase = (n0 >> 2) + wn * 8;
    const int sub = (lane & 1);
#pragma unroll
    for (int i = 0; i < 4; i++) {
        const int mrow = mbase + i * 16 + (lane >> 2) + sub * 8;
        const bool valid = (mrow < M);
        const long long mb = (long long)mrow * HSZ;
#pragma unroll
        for (int j = 0; j < 4; j++) {
            float v0 = acc[i][j][0], v1 = acc[i][j][1];
            float v2 = acc[i][j][2], v3 = acc[i][j][3];
            float x0 = __shfl_xor_sync(0xFFFFFFFF, v0, 1);
            float x1 = __shfl_xor_sync(0xFFFFFFFF, v1, 1);
            float x2 = __shfl_xor_sync(0xFFFFFFFF, v2, 1);
            float x3 = __shfl_xor_sync(0xFFFFFFFF, v3, 1);
            float zi, zo, zu, zf;
            if (sub == 0) { zi = v0; zo = v1; zu = x0; zf = x1; }
            else          { zi = x2; zo = x3; zu = v2; zf = v3; }
            const int q = qbase + j * 2 + ((lane & 3) >> 1);
            const int ql = q - (n0 >> 2);
            float4 b4 = ((const float4*)s_bias)[ql];
            zi += b4.x; zo += b4.y; zu += b4.z; zf += b4.w;
            if (valid) {
                float cs = g_csum[mb + q];
                float cn = sig_(zi) * tanh_(zu) + sig_(zf) * cs;
                float hn = sig_(zo) * tanh_(cn);
                hout[mb + q] = hn;
                cout[mb + q] = cn;
            }
        }
    }
}

// ---------------------------------------------------------------------------
// launch
// ---------------------------------------------------------------------------
extern "C" void kernel_launch(void* const* d_in, const int* in_sizes, int n_in,
                              void* d_out, int out_size) {
    const float* x    = (const float*)d_in[0];
    const float* h    = (const float*)d_in[1];
    const float* c    = (const float*)d_in[2];
    const int*   src  = (const int*)d_in[3];
    const int*   dst  = (const int*)d_in[4];
    const float* Wiou = (const float*)d_in[5];
    const float* Uiou = (const float*)d_in[6];
    const float* biou = (const float*)d_in[7];
    const float* Ufw  = (const float*)d_in[8];
    const float* Ufb  = (const float*)d_in[9];

    const int E = in_sizes[3];
    const int M = in_sizes[0] / XSZ;

    float* hout = (float*)d_out;
    float* cout = (float*)d_out + (long long)M * HSZ;

    cudaFuncSetAttribute(gemm_mma_kernel,
                         cudaFuncAttributeMaxDynamicSharedMemorySize, DYN_SMEM);

    zero_kernel<<<4096, 256>>>();
    pack_kernel<<<(NOUT * KK + 255) / 256, 256>>>(Wiou, Uiou, biou, Ufw, Ufb);
    scatter_kernel<<<(E + 3) / 4, 256>>>(h, c, src, dst, E);
    convert_kernel<<<(int)(((long long)M * 128 + 255) / 256), 256>>>(x, M);

    dim3 grid(NOUT / 128, (M + 127) / 128);
    gemm_mma_kernel<<<grid, 256, DYN_SMEM>>>(hout, cout, M);
}

// round 4
// speedup vs baseline: 2.1876x; 1.2284x over previous
#include <cuda_runtime.h>
#include <cuda_fp16.h>
#include <math.h>
#include <stdint.h>

// Problem constants (fixed by the dataset)
#define NNODES 200000
#define HSZ    256
#define XSZ    256
#define KK     512          // packed K = XSZ + HSZ
#define NOUT   1024         // packed cols, interleaved gate quads (i,o,u,f)

// ---------------- device scratch (static allocation) ------------------------
__device__ float g_hsum[NNODES * HSZ];                 // 200 MB
__device__ float g_csum[NNODES * HSZ];                 // 200 MB
__device__ __half g_Af[(size_t)NNODES * KK];           // 204.8 MB  A = [x|hsum] fp16
__device__ __half g_Bh[NOUT * KK];                     // 1 MB  [n][k] K-major
__device__ __half g_Bl[NOUT * KK];                     // 1 MB
__device__ float g_bias[NOUT];

// ---------------- PTX helpers (baseline compute_103 only) -------------------
__device__ __forceinline__ uint32_t s2u(const void* p) {
    uint32_t a;
    asm("{ .reg .u64 t; cvta.to.shared.u64 t, %1; cvt.u32.u64 %0, t; }"
        : "=r"(a) : "l"(p));
    return a;
}
#define CPA16(dst, src) \
    asm volatile("cp.async.cg.shared.global [%0], [%1], 16;" :: "r"(dst), "l"(src) : "memory")
#define CPA_COMMIT() asm volatile("cp.async.commit_group;" ::: "memory")

__device__ __forceinline__ void ldsm4(uint32_t* r, uint32_t addr) {
    asm volatile("ldmatrix.sync.aligned.m8n8.x4.shared.b16 {%0,%1,%2,%3}, [%4];"
                 : "=r"(r[0]), "=r"(r[1]), "=r"(r[2]), "=r"(r[3]) : "r"(addr));
}
__device__ __forceinline__ void mma16816(float* d, const uint32_t* a, const uint32_t* b) {
    asm volatile("mma.sync.aligned.m16n8k16.row.col.f32.f16.f16.f32 "
                 "{%0,%1,%2,%3}, {%4,%5,%6,%7}, {%8,%9}, {%0,%1,%2,%3};"
                 : "+f"(d[0]), "+f"(d[1]), "+f"(d[2]), "+f"(d[3])
                 : "r"(a[0]), "r"(a[1]), "r"(a[2]), "r"(a[3]), "r"(b[0]), "r"(b[1]));
}

// fast sigmoid/tanh via ex2/rcp approx (rel err ~1e-6)
__device__ __forceinline__ float fexp2_(float x) {
    float y; asm("ex2.approx.ftz.f32 %0, %1;" : "=f"(y) : "f"(x)); return y;
}
__device__ __forceinline__ float frcp_(float x) {
    float y; asm("rcp.approx.ftz.f32 %0, %1;" : "=f"(y) : "f"(x)); return y;
}
__device__ __forceinline__ float sig_(float x) {
    return frcp_(1.0f + fexp2_(-1.4426950408889634f * x));
}
__device__ __forceinline__ float tanh_(float x) {
    return 2.0f * frcp_(1.0f + fexp2_(-2.8853900817779268f * x)) - 1.0f;
}

// ---------------------------------------------------------------------------
// Kernel 0: zero accumulators
// ---------------------------------------------------------------------------
__global__ void zero_kernel() {
    long long idx = (long long)blockIdx.x * blockDim.x + threadIdx.x;
    long long total4 = (long long)NNODES * HSZ / 4;
    float4 z = make_float4(0.f, 0.f, 0.f, 0.f);
    for (long long i = idx; i < total4; i += (long long)gridDim.x * blockDim.x) {
        ((float4*)g_hsum)[i] = z;
        ((float4*)g_csum)[i] = z;
    }
}

// ---------------------------------------------------------------------------
// Kernel 1: pack weights -> fp16 hi/lo, layout [n][k] K-major, n = 4q+t
//   b_hi + b_lo captures the fp32 weight to ~2^-22 (fp16 subnormals OK)
// ---------------------------------------------------------------------------
__global__ void pack_kernel(const float* __restrict__ Wiou,
                            const float* __restrict__ Uiou,
                            const float* __restrict__ biou,
                            const float* __restrict__ Ufw,
                            const float* __restrict__ Ufb) {
    int idx = blockIdx.x * blockDim.x + threadIdx.x;
    if (idx < NOUT * KK) {
        int n = idx >> 9;
        int k = idx & (KK - 1);
        int q = n >> 2;
        int t = n & 3;
        float v;
        if (k < 256) {
            v = (t < 3) ? Wiou[(t * 256 + q) * XSZ + k] : 0.0f;
        } else {
            int kk = k - 256;
            v = (t < 3) ? Uiou[(t * 256 + q) * HSZ + kk] : Ufw[q * HSZ + kk];
        }
        __half hi = __float2half_rn(v);
        __half lo = __float2half_rn(v - __half2float(hi));
        g_Bh[idx] = hi;
        g_Bl[idx] = lo;
    }
    if (idx < NOUT) {
        int q = idx >> 2;
        int t = idx & 3;
        g_bias[idx] = (t < 3) ? biou[t * 256 + q] : Ufb[q];
    }
}

// ---------------------------------------------------------------------------
// Kernel 2: edge scatter-add
// ---------------------------------------------------------------------------
__global__ void scatter_kernel(const float* __restrict__ h,
                               const float* __restrict__ c,
                               const int* __restrict__ src,
                               const int* __restrict__ dst,
                               int E) {
    int e = blockIdx.x * 4 + (threadIdx.x >> 6);
    if (e >= E) return;
    int lane = threadIdx.x & 63;
    int s = src[e];
    int d = dst[e];
    int off = lane * 4;
    float4 hv = *(const float4*)&h[(long long)s * HSZ + off];
    float4 cv = *(const float4*)&c[(long long)s * HSZ + off];
    float* hp = &g_hsum[(long long)d * HSZ + off];
    float* cp = &g_csum[(long long)d * HSZ + off];
    atomicAdd(hp + 0, hv.x); atomicAdd(hp + 1, hv.y);
    atomicAdd(hp + 2, hv.z); atomicAdd(hp + 3, hv.w);
    atomicAdd(cp + 0, cv.x); atomicAdd(cp + 1, cv.y);
    atomicAdd(cp + 2, cv.z); atomicAdd(cp + 3, cv.w);
}

// ---------------------------------------------------------------------------
// Kernel 3: convert A = [x | hsum] -> fp16 [m][512]
// ---------------------------------------------------------------------------
__global__ void convert_kernel(const float* __restrict__ x, int M) {
    long long i = (long long)blockIdx.x * blockDim.x + threadIdx.x;
    long long total = (long long)M * 128;          // one float4 each
    if (i >= total) return;
    int m = (int)(i >> 7);
    int k = ((int)i & 127) * 4;
    const float* sp = (k < 256) ? &x[(long long)m * 256 + k]
                                : &g_hsum[(long long)m * 256 + (k - 256)];
    float4 v = *(const float4*)sp;
    __half2 h01 = __floats2half2_rn(v.x, v.y);
    __half2 h23 = __floats2half2_rn(v.z, v.w);
    long long off = (long long)m * KK + k;
    *(__half2*)&g_Af[off + 0] = h01;
    *(__half2*)&g_Af[off + 2] = h23;
}

// ---------------------------------------------------------------------------
// Kernel 4: fp16 mma.sync GEMM (128x128xK512, B hi/lo 2-pass) + fused epilogue
//   smem stage: A / Bh / Bl tiles, 128 rows x 32 half, padded row = 80 B
// ---------------------------------------------------------------------------
#define BK        32
#define ROWB      80                       // padded row bytes (40 halves)
#define SEC_B     (128 * ROWB)             // 10240 B per matrix section
#define STAGE_B   (3 * SEC_B)              // 30720 B
#define NSTG      3
#define KITERS    (KK / BK)                // 16
#define DYN_SMEM  (NSTG * STAGE_B)         // 92160 B

__global__ void __launch_bounds__(256, 1)
gemm_mma_kernel(float* __restrict__ hout, float* __restrict__ cout, int M) {
    extern __shared__ __align__(128) char sm[];
    __shared__ float s_bias[128];

    const int tid  = threadIdx.x;
    const int lane = tid & 31;
    const int wid  = tid >> 5;
    const int wm   = wid >> 2;            // 0..1  (64-row band)
    const int wn   = wid & 3;             // 0..3  (32-col band)
    const int m0   = blockIdx.y * 128;
    const int n0   = blockIdx.x * 128;
    const uint32_t smb = s2u(sm);

    if (tid < 128) s_bias[tid] = g_bias[n0 + tid];

    // ---- stage loader: 1536 x 16B cp.async ---------------------------------
    auto load_stage = [&](int s) {
        const uint32_t base = smb + (s % NSTG) * STAGE_B;
        const int k0 = s * BK;
#pragma unroll
        for (int i = 0; i < 6; i++) {
            int l = tid + i * 256;
            int sec = l >> 9;             // 0=A 1=Bh 2=Bl
            int w = l & 511;
            int row = w >> 2;
            int ch = w & 3;
            const __half* src;
            if (sec == 0) {
                int gr = m0 + row; if (gr >= M) gr = M - 1;
                src = g_Af + (long long)gr * KK + k0 + ch * 8;
            } else {
                const __half* g = (sec == 2) ? g_Bl : g_Bh;
                src = g + (long long)(n0 + row) * KK + k0 + ch * 8;
            }
            uint32_t dst = base + sec * SEC_B + row * ROWB + ch * 16;
            CPA16(dst, src);
        }
        CPA_COMMIT();
    };

    load_stage(0);
    load_stage(1);
    load_stage(2);

    float acc[4][4][4];
#pragma unroll
    for (int i = 0; i < 4; i++)
#pragma unroll
        for (int j = 0; j < 4; j++)
#pragma unroll
            for (int p = 0; p < 4; p++) acc[i][j][p] = 0.0f;

    for (int s = 0; s < KITERS; s++) {
        if (s <= KITERS - 3)      asm volatile("cp.async.wait_group 2;" ::: "memory");
        else if (s == KITERS - 2) asm volatile("cp.async.wait_group 1;" ::: "memory");
        else                      asm volatile("cp.async.wait_group 0;" ::: "memory");
        __syncthreads();

        const uint32_t base = smb + (s % NSTG) * STAGE_B;
        const uint32_t aRow = (wm * 64 + (lane & 15)) * ROWB + (lane >> 4) * 16;
        const uint32_t bRow = (wn * 32 + (lane & 7) + ((lane >> 4) & 1) * 8) * ROWB
                              + ((lane >> 3) & 1) * 16;

#pragma unroll
        for (int t = 0; t < 2; t++) {
            const uint32_t kb = t * 32;
            uint32_t ah[4][4], bh[2][4], bl[2][4];
#pragma unroll
            for (int i = 0; i < 4; i++)
                ldsm4(ah[i], base + 0 * SEC_B + aRow + i * 16 * ROWB + kb);
#pragma unroll
            for (int j = 0; j < 2; j++) {
                ldsm4(bh[j], base + 1 * SEC_B + bRow + j * 16 * ROWB + kb);
                ldsm4(bl[j], base + 2 * SEC_B + bRow + j * 16 * ROWB + kb);
            }
#pragma unroll
            for (int i = 0; i < 4; i++) {
#pragma unroll
                for (int jt = 0; jt < 4; jt++) {
                    const uint32_t* bp_h = &bh[jt >> 1][(jt & 1) * 2];
                    const uint32_t* bp_l = &bl[jt >> 1][(jt & 1) * 2];
                    mma16816(acc[i][jt], ah[i], bp_h);
                    mma16816(acc[i][jt], ah[i], bp_l);
                }
            }
        }
        __syncthreads();
        if (s + NSTG < KITERS) load_stage(s + NSTG);
    }

    // ---- fused TreeLSTM epilogue ------------------------------------------
    // pair lanes (l, l^1) reassemble one full (i,o,u,f) quad via shfl.
    const int mbase = m0 + wm * 64;
    const int qbase = (n0 >> 2) + wn * 8;
    const int sub = (lane & 1);
#pragma unroll
    for (int i = 0; i < 4; i++) {
        const int mrow = mbase + i * 16 + (lane >> 2) + sub * 8;
        const bool valid = (mrow < M);
        const long long mb = (long long)mrow * HSZ;
#pragma unroll
        for (int j = 0; j < 4; j++) {
            float v0 = acc[i][j][0], v1 = acc[i][j][1];
            float v2 = acc[i][j][2], v3 = acc[i][j][3];
            float x0 = __shfl_xor_sync(0xFFFFFFFF, v0, 1);
            float x1 = __shfl_xor_sync(0xFFFFFFFF, v1, 1);
            float x2 = __shfl_xor_sync(0xFFFFFFFF, v2, 1);
            float x3 = __shfl_xor_sync(0xFFFFFFFF, v3, 1);
            float zi, zo, zu, zf;
            if (sub == 0) { zi = v0; zo = v1; zu = x0; zf = x1; }
            else          { zi = x2; zo = x3; zu = v2; zf = v3; }
            const int q = qbase + j * 2 + ((lane & 3) >> 1);
            const int ql = q - (n0 >> 2);
            float4 b4 = ((const float4*)s_bias)[ql];
            zi += b4.x; zo += b4.y; zu += b4.z; zf += b4.w;
            if (valid) {
                float cs = g_csum[mb + q];
                float cn = sig_(zi) * tanh_(zu) + sig_(zf) * cs;
                float hn = sig_(zo) * tanh_(cn);
                hout[mb + q] = hn;
                cout[mb + q] = cn;
            }
        }
    }
}

// ---------------------------------------------------------------------------
// launch
// ---------------------------------------------------------------------------
extern "C" void kernel_launch(void* const* d_in, const int* in_sizes, int n_in,
                              void* d_out, int out_size) {
    const float* x    = (const float*)d_in[0];
    const float* h    = (const float*)d_in[1];
    const float* c    = (const float*)d_in[2];
    const int*   src  = (const int*)d_in[3];
    const int*   dst  = (const int*)d_in[4];
    const float* Wiou = (const float*)d_in[5];
    const float* Uiou = (const float*)d_in[6];
    const float* biou = (const float*)d_in[7];
    const float* Ufw  = (const float*)d_in[8];
    const float* Ufb  = (const float*)d_in[9];

    const int E = in_sizes[3];
    const int M = in_sizes[0] / XSZ;

    float* hout = (float*)d_out;
    float* cout = (float*)d_out + (long long)M * HSZ;

    cudaFuncSetAttribute(gemm_mma_kernel,
                         cudaFuncAttributeMaxDynamicSharedMemorySize, DYN_SMEM);

    zero_kernel<<<4096, 256>>>();
    pack_kernel<<<(NOUT * KK + 255) / 256, 256>>>(Wiou, Uiou, biou, Ufw, Ufb);
    scatter_kernel<<<(E + 3) / 4, 256>>>(h, c, src, dst, E);
    convert_kernel<<<(int)(((long long)M * 128 + 255) / 256), 256>>>(x, M);

    dim3 grid(NOUT / 128, (M + 127) / 128);
    gemm_mma_kernel<<<grid, 256, DYN_SMEM>>>(hout, cout, M);
}

// round 5
// speedup vs baseline: 3.7815x; 1.7286x over previous
#include <cuda_runtime.h>
#include <cuda_fp16.h>
#include <math.h>
#include <stdint.h>

// Problem constants (fixed by the dataset)
#define NNODES 200000
#define HSZ    256
#define XSZ    256
#define KK     512          // packed K = XSZ + HSZ
#define NOUT   1024         // packed cols, interleaved gate quads (i,o,u,f)

// ---------------- device scratch (static allocation) ------------------------
__device__ float g_hsum[NNODES * HSZ];                 // 200 MB
__device__ float g_csum[NNODES * HSZ];                 // 200 MB
__device__ __half g_Af[(size_t)NNODES * KK];           // 204.8 MB  A = [x|hsum] fp16
__device__ __half g_Bf[NOUT * KK];                     // 1 MB  [n][k] K-major
__device__ float g_bias[NOUT];

// ---------------- PTX helpers (baseline compute_103 only) -------------------
__device__ __forceinline__ uint32_t s2u(const void* p) {
    uint32_t a;
    asm("{ .reg .u64 t; cvta.to.shared.u64 t, %1; cvt.u32.u64 %0, t; }"
        : "=r"(a) : "l"(p));
    return a;
}
#define CPA16(dst, src) \
    asm volatile("cp.async.cg.shared.global [%0], [%1], 16;" :: "r"(dst), "l"(src) : "memory")
#define CPA_COMMIT() asm volatile("cp.async.commit_group;" ::: "memory")

__device__ __forceinline__ void ldsm4(uint32_t* r, uint32_t addr) {
    asm volatile("ldmatrix.sync.aligned.m8n8.x4.shared.b16 {%0,%1,%2,%3}, [%4];"
                 : "=r"(r[0]), "=r"(r[1]), "=r"(r[2]), "=r"(r[3]) : "r"(addr));
}
__device__ __forceinline__ void mma16816(float* d, const uint32_t* a, const uint32_t* b) {
    asm volatile("mma.sync.aligned.m16n8k16.row.col.f32.f16.f16.f32 "
                 "{%0,%1,%2,%3}, {%4,%5,%6,%7}, {%8,%9}, {%0,%1,%2,%3};"
                 : "+f"(d[0]), "+f"(d[1]), "+f"(d[2]), "+f"(d[3])
                 : "r"(a[0]), "r"(a[1]), "r"(a[2]), "r"(a[3]), "r"(b[0]), "r"(b[1]));
}

// fast sigmoid/tanh via ex2/rcp approx (rel err ~1e-6)
__device__ __forceinline__ float fexp2_(float x) {
    float y; asm("ex2.approx.ftz.f32 %0, %1;" : "=f"(y) : "f"(x)); return y;
}
__device__ __forceinline__ float frcp_(float x) {
    float y; asm("rcp.approx.ftz.f32 %0, %1;" : "=f"(y) : "f"(x)); return y;
}
__device__ __forceinline__ float sig_(float x) {
    return frcp_(1.0f + fexp2_(-1.4426950408889634f * x));
}
__device__ __forceinline__ float tanh_(float x) {
    return 2.0f * frcp_(1.0f + fexp2_(-2.8853900817779268f * x)) - 1.0f;
}

// ---------------------------------------------------------------------------
// Kernel 0: zero accumulators
// ---------------------------------------------------------------------------
__global__ void zero_kernel() {
    long long idx = (long long)blockIdx.x * blockDim.x + threadIdx.x;
    long long total4 = (long long)NNODES * HSZ / 4;
    float4 z = make_float4(0.f, 0.f, 0.f, 0.f);
    for (long long i = idx; i < total4; i += (long long)gridDim.x * blockDim.x) {
        ((float4*)g_hsum)[i] = z;
        ((float4*)g_csum)[i] = z;
    }
}

// ---------------------------------------------------------------------------
// Kernel 1: pack weights -> fp16, layout [n][k] K-major, n = 4q+t
// ---------------------------------------------------------------------------
__global__ void pack_kernel(const float* __restrict__ Wiou,
                            const float* __restrict__ Uiou,
                            const float* __restrict__ biou,
                            const float* __restrict__ Ufw,
                            const float* __restrict__ Ufb) {
    int idx = blockIdx.x * blockDim.x + threadIdx.x;
    if (idx < NOUT * KK) {
        int n = idx >> 9;
        int k = idx & (KK - 1);
        int q = n >> 2;
        int t = n & 3;
        float v;
        if (k < 256) {
            v = (t < 3) ? Wiou[(t * 256 + q) * XSZ + k] : 0.0f;
        } else {
            int kk = k - 256;
            v = (t < 3) ? Uiou[(t * 256 + q) * HSZ + kk] : Ufw[q * HSZ + kk];
        }
        g_Bf[idx] = __float2half_rn(v);
    }
    if (idx < NOUT) {
        int q = idx >> 2;
        int t = idx & 3;
        g_bias[idx] = (t < 3) ? biou[t * 256 + q] : Ufb[q];
    }
}

// ---------------------------------------------------------------------------
// Kernel 2: edge scatter-add
// ---------------------------------------------------------------------------
__global__ void scatter_kernel(const float* __restrict__ h,
                               const float* __restrict__ c,
                               const int* __restrict__ src,
                               const int* __restrict__ dst,
                               int E) {
    int e = blockIdx.x * 4 + (threadIdx.x >> 6);
    if (e >= E) return;
    int lane = threadIdx.x & 63;
    int s = src[e];
    int d = dst[e];
    int off = lane * 4;
    float4 hv = *(const float4*)&h[(long long)s * HSZ + off];
    float4 cv = *(const float4*)&c[(long long)s * HSZ + off];
    float* hp = &g_hsum[(long long)d * HSZ + off];
    float* cp = &g_csum[(long long)d * HSZ + off];
    atomicAdd(hp + 0, hv.x); atomicAdd(hp + 1, hv.y);
    atomicAdd(hp + 2, hv.z); atomicAdd(hp + 3, hv.w);
    atomicAdd(cp + 0, cv.x); atomicAdd(cp + 1, cv.y);
    atomicAdd(cp + 2, cv.z); atomicAdd(cp + 3, cv.w);
}

// ---------------------------------------------------------------------------
// Kernel 3: convert A = [x | hsum] -> fp16 [m][512]
// ---------------------------------------------------------------------------
__global__ void convert_kernel(const float* __restrict__ x, int M) {
    long long i = (long long)blockIdx.x * blockDim.x + threadIdx.x;
    long long total = (long long)M * 128;          // one float4 each
    if (i >= total) return;
    int m = (int)(i >> 7);
    int k = ((int)i & 127) * 4;
    const float* sp = (k < 256) ? &x[(long long)m * 256 + k]
                                : &g_hsum[(long long)m * 256 + (k - 256)];
    float4 v = *(const float4*)sp;
    __half2 h01 = __floats2half2_rn(v.x, v.y);
    __half2 h23 = __floats2half2_rn(v.z, v.w);
    long long off = (long long)m * KK + k;
    *(__half2*)&g_Af[off + 0] = h01;
    *(__half2*)&g_Af[off + 2] = h23;
}

// ---------------------------------------------------------------------------
// Kernel 4: fp16 mma.sync GEMM (128x128xK512, single pass) + fused epilogue
//   smem stage: A / B tiles, 128 rows x 32 half, padded row = 80 B
// ---------------------------------------------------------------------------
#define BK        32
#define ROWB      80                       // padded row bytes (40 halves)
#define SEC_B     (128 * ROWB)             // 10240 B per matrix section
#define STAGE_B   (2 * SEC_B)              // 20480 B
#define NSTG      3
#define KITERS    (KK / BK)                // 16
#define DYN_SMEM  (NSTG * STAGE_B)         // 61440 B

__global__ void __launch_bounds__(256, 2)
gemm_mma_kernel(float* __restrict__ hout, float* __restrict__ cout, int M) {
    extern __shared__ __align__(128) char sm[];
    __shared__ float s_bias[128];

    const int tid  = threadIdx.x;
    const int lane = tid & 31;
    const int wid  = tid >> 5;
    const int wm   = wid >> 2;            // 0..1  (64-row band)
    const int wn   = wid & 3;             // 0..3  (32-col band)
    const int m0   = blockIdx.y * 128;
    const int n0   = blockIdx.x * 128;
    const uint32_t smb = s2u(sm);

    if (tid < 128) s_bias[tid] = g_bias[n0 + tid];

    // ---- stage loader: 1024 x 16B cp.async ---------------------------------
    auto load_stage = [&](int s) {
        const uint32_t base = smb + (s % NSTG) * STAGE_B;
        const int k0 = s * BK;
#pragma unroll
        for (int i = 0; i < 4; i++) {
            int l = tid + i * 256;
            int sec = l >> 9;             // 0=A 1=B
            int w = l & 511;
            int row = w >> 2;
            int ch = w & 3;
            const __half* src;
            if (sec == 0) {
                int gr = m0 + row; if (gr >= M) gr = M - 1;
                src = g_Af + (long long)gr * KK + k0 + ch * 8;
            } else {
                src = g_Bf + (long long)(n0 + row) * KK + k0 + ch * 8;
            }
            uint32_t dst = base + sec * SEC_B + row * ROWB + ch * 16;
            CPA16(dst, src);
        }
        CPA_COMMIT();
    };

    load_stage(0);
    load_stage(1);
    load_stage(2);

    float acc[4][4][4];
#pragma unroll
    for (int i = 0; i < 4; i++)
#pragma unroll
        for (int j = 0; j < 4; j++)
#pragma unroll
            for (int p = 0; p < 4; p++) acc[i][j][p] = 0.0f;

    for (int s = 0; s < KITERS; s++) {
        if (s <= KITERS - 3)      asm volatile("cp.async.wait_group 2;" ::: "memory");
        else if (s == KITERS - 2) asm volatile("cp.async.wait_group 1;" ::: "memory");
        else                      asm volatile("cp.async.wait_group 0;" ::: "memory");
        __syncthreads();

        const uint32_t base = smb + (s % NSTG) * STAGE_B;
        const uint32_t aRow = (wm * 64 + (lane & 15)) * ROWB + (lane >> 4) * 16;
        const uint32_t bRow = (wn * 32 + (lane & 7) + ((lane >> 4) & 1) * 8) * ROWB
                              + ((lane >> 3) & 1) * 16;

#pragma unroll
        for (int t = 0; t < 2; t++) {
            const uint32_t kb = t * 32;
            uint32_t ah[4][4], bh[2][4];
#pragma unroll
            for (int i = 0; i < 4; i++)
                ldsm4(ah[i], base + 0 * SEC_B + aRow + i * 16 * ROWB + kb);
#pragma unroll
            for (int j = 0; j < 2; j++)
                ldsm4(bh[j], base + 1 * SEC_B + bRow + j * 16 * ROWB + kb);
#pragma unroll
            for (int i = 0; i < 4; i++) {
#pragma unroll
                for (int jt = 0; jt < 4; jt++) {
                    mma16816(acc[i][jt], ah[i], &bh[jt >> 1][(jt & 1) * 2]);
                }
            }
        }
        __syncthreads();
        if (s + NSTG < KITERS) load_stage(s + NSTG);
    }

    // ---- fused TreeLSTM epilogue ------------------------------------------
    // pair lanes (l, l^1) reassemble one full (i,o,u,f) quad via shfl.
    const int mbase = m0 + wm * 64;
    const int qbase = (n0 >> 2) + wn * 8;
    const int sub = (lane & 1);
#pragma unroll
    for (int i = 0; i < 4; i++) {
        const int mrow = mbase + i * 16 + (lane >> 2) + sub * 8;
        const bool valid = (mrow < M);
        const long long mb = (long long)mrow * HSZ;
#pragma unroll
        for (int j = 0; j < 4; j++) {
            float v0 = acc[i][j][0], v1 = acc[i][j][1];
            float v2 = acc[i][j][2], v3 = acc[i][j][3];
            float x0 = __shfl_xor_sync(0xFFFFFFFF, v0, 1);
            float x1 = __shfl_xor_sync(0xFFFFFFFF, v1, 1);
            float x2 = __shfl_xor_sync(0xFFFFFFFF, v2, 1);
            float x3 = __shfl_xor_sync(0xFFFFFFFF, v3, 1);
            float zi, zo, zu, zf;
            if (sub == 0) { zi = v0; zo = v1; zu = x0; zf = x1; }
            else          { zi = x2; zo = x3; zu = v2; zf = v3; }
            const int q = qbase + j * 2 + ((lane & 3) >> 1);
            const int ql = q - (n0 >> 2);
            float4 b4 = ((const float4*)s_bias)[ql];
            zi += b4.x; zo += b4.y; zu += b4.z; zf += b4.w;
            if (valid) {
                float cs = g_csum[mb + q];
                float cn = sig_(zi) * tanh_(zu) + sig_(zf) * cs;
                float hn = sig_(zo) * tanh_(cn);
                hout[mb + q] = hn;
                cout[mb + q] = cn;
            }
        }
    }
}

// ---------------------------------------------------------------------------
// launch
// ---------------------------------------------------------------------------
extern "C" void kernel_launch(void* const* d_in, const int* in_sizes, int n_in,
                              void* d_out, int out_size) {
    const float* x    = (const float*)d_in[0];
    const float* h    = (const float*)d_in[1];
    const float* c    = (const float*)d_in[2];
    const int*   src  = (const int*)d_in[3];
    const int*   dst  = (const int*)d_in[4];
    const float* Wiou = (const float*)d_in[5];
    const float* Uiou = (const float*)d_in[6];
    const float* biou = (const float*)d_in[7];
    const float* Ufw  = (const float*)d_in[8];
    const float* Ufb  = (const float*)d_in[9];

    const int E = in_sizes[3];
    const int M = in_sizes[0] / XSZ;

    float* hout = (float*)d_out;
    float* cout = (float*)d_out + (long long)M * HSZ;

    cudaFuncSetAttribute(gemm_mma_kernel,
                         cudaFuncAttributeMaxDynamicSharedMemorySize, DYN_SMEM);

    zero_kernel<<<4096, 256>>>();
    pack_kernel<<<(NOUT * KK + 255) / 256, 256>>>(Wiou, Uiou, biou, Ufw, Ufb);
    scatter_kernel<<<(E + 3) / 4, 256>>>(h, c, src, dst, E);
    convert_kernel<<<(int)(((long long)M * 128 + 255) / 256), 256>>>(x, M);

    dim3 grid(NOUT / 128, (M + 127) / 128);
    gemm_mma_kernel<<<grid, 256, DYN_SMEM>>>(hout, cout, M);
}

// round 6
// speedup vs baseline: 4.0988x; 1.0839x over previous
#include <cuda_runtime.h>
#include <cuda_fp16.h>
#include <math.h>
#include <stdint.h>

// Problem constants (fixed by the dataset)
#define NNODES 200000
#define HSZ    256
#define XSZ    256
#define KK     512          // packed K = XSZ + HSZ
#define NOUT   1024         // packed cols, interleaved gate quads (i,o,u,f)

// ---------------- device scratch (static allocation) ------------------------
__device__ float g_hsum[NNODES * HSZ];                 // 200 MB
__device__ float g_csum[NNODES * HSZ];                 // 200 MB
__device__ __half g_Af[(size_t)NNODES * KK];           // 204.8 MB  A = [x|hsum] fp16
__device__ __half g_Bf[NOUT * KK];                     // 1 MB  [n][k] K-major
__device__ float g_bias[NOUT];

// ---------------- PTX helpers (baseline compute_103 only) -------------------
__device__ __forceinline__ uint32_t s2u(const void* p) {
    uint32_t a;
    asm("{ .reg .u64 t; cvta.to.shared.u64 t, %1; cvt.u32.u64 %0, t; }"
        : "=r"(a) : "l"(p));
    return a;
}
#define CPA16(dst, src) \
    asm volatile("cp.async.cg.shared.global [%0], [%1], 16;" :: "r"(dst), "l"(src) : "memory")
#define CPA_COMMIT() asm volatile("cp.async.commit_group;" ::: "memory")

__device__ __forceinline__ void ldsm4(uint32_t* r, uint32_t addr) {
    asm volatile("ldmatrix.sync.aligned.m8n8.x4.shared.b16 {%0,%1,%2,%3}, [%4];"
                 : "=r"(r[0]), "=r"(r[1]), "=r"(r[2]), "=r"(r[3]) : "r"(addr));
}
__device__ __forceinline__ void mma16816(float* d, const uint32_t* a, const uint32_t* b) {
    asm volatile("mma.sync.aligned.m16n8k16.row.col.f32.f16.f16.f32 "
                 "{%0,%1,%2,%3}, {%4,%5,%6,%7}, {%8,%9}, {%0,%1,%2,%3};"
                 : "+f"(d[0]), "+f"(d[1]), "+f"(d[2]), "+f"(d[3])
                 : "r"(a[0]), "r"(a[1]), "r"(a[2]), "r"(a[3]), "r"(b[0]), "r"(b[1]));
}
// vectorized f32 reduction (PTX ISA 8.1+, sm_90+, not arch-'a' gated)
__device__ __forceinline__ void red_add_v4(float* p, float4 v) {
    asm volatile("red.add.v4.f32 [%0], {%1, %2, %3, %4};"
                 :: "l"(p), "f"(v.x), "f"(v.y), "f"(v.z), "f"(v.w) : "memory");
}

// fast sigmoid/tanh via ex2/rcp approx (rel err ~1e-6)
__device__ __forceinline__ float fexp2_(float x) {
    float y; asm("ex2.approx.ftz.f32 %0, %1;" : "=f"(y) : "f"(x)); return y;
}
__device__ __forceinline__ float frcp_(float x) {
    float y; asm("rcp.approx.ftz.f32 %0, %1;" : "=f"(y) : "f"(x)); return y;
}
__device__ __forceinline__ float sig_(float x) {
    return frcp_(1.0f + fexp2_(-1.4426950408889634f * x));
}
__device__ __forceinline__ float tanh_(float x) {
    return 2.0f * frcp_(1.0f + fexp2_(-2.8853900817779268f * x)) - 1.0f;
}

// ---------------------------------------------------------------------------
// Kernel 0: zero accumulators
// ---------------------------------------------------------------------------
__global__ void zero_kernel() {
    long long idx = (long long)blockIdx.x * blockDim.x + threadIdx.x;
    long long total4 = (long long)NNODES * HSZ / 4;
    float4 z = make_float4(0.f, 0.f, 0.f, 0.f);
    for (long long i = idx; i < total4; i += (long long)gridDim.x * blockDim.x) {
        ((float4*)g_hsum)[i] = z;
        ((float4*)g_csum)[i] = z;
    }
}

// ---------------------------------------------------------------------------
// Kernel 1: pack weights -> fp16, layout [n][k] K-major, n = 4q+t
// ---------------------------------------------------------------------------
__global__ void pack_kernel(const float* __restrict__ Wiou,
                            const float* __restrict__ Uiou,
                            const float* __restrict__ biou,
                            const float* __restrict__ Ufw,
                            const float* __restrict__ Ufb) {
    int idx = blockIdx.x * blockDim.x + threadIdx.x;
    if (idx < NOUT * KK) {
        int n = idx >> 9;
        int k = idx & (KK - 1);
        int q = n >> 2;
        int t = n & 3;
        float v;
        if (k < 256) {
            v = (t < 3) ? Wiou[(t * 256 + q) * XSZ + k] : 0.0f;
        } else {
            int kk = k - 256;
            v = (t < 3) ? Uiou[(t * 256 + q) * HSZ + kk] : Ufw[q * HSZ + kk];
        }
        g_Bf[idx] = __float2half_rn(v);
    }
    if (idx < NOUT) {
        int q = idx >> 2;
        int t = idx & 3;
        g_bias[idx] = (t < 3) ? biou[t * 256 + q] : Ufb[q];
    }
}

// ---------------------------------------------------------------------------
// Kernel 2: edge scatter-add with vectorized f32 reductions
// ---------------------------------------------------------------------------
__global__ void scatter_kernel(const float* __restrict__ h,
                               const float* __restrict__ c,
                               const int* __restrict__ src,
                               const int* __restrict__ dst,
                               int E) {
    int e = blockIdx.x * 4 + (threadIdx.x >> 6);
    if (e >= E) return;
    int lane = threadIdx.x & 63;
    int s = src[e];
    int d = dst[e];
    int off = lane * 4;
    float4 hv = *(const float4*)&h[(long long)s * HSZ + off];
    float4 cv = *(const float4*)&c[(long long)s * HSZ + off];
    red_add_v4(&g_hsum[(long long)d * HSZ + off], hv);
    red_add_v4(&g_csum[(long long)d * HSZ + off], cv);
}

// ---------------------------------------------------------------------------
// Kernel 3: convert A = [x | hsum] -> fp16 [m][512]
// ---------------------------------------------------------------------------
__global__ void convert_kernel(const float* __restrict__ x, int M) {
    long long i = (long long)blockIdx.x * blockDim.x + threadIdx.x;
    long long total = (long long)M * 128;          // one float4 each
    if (i >= total) return;
    int m = (int)(i >> 7);
    int k = ((int)i & 127) * 4;
    const float* sp = (k < 256) ? &x[(long long)m * 256 + k]
                                : &g_hsum[(long long)m * 256 + (k - 256)];
    float4 v = *(const float4*)sp;
    __half2 h01 = __floats2half2_rn(v.x, v.y);
    __half2 h23 = __floats2half2_rn(v.z, v.w);
    long long off = (long long)m * KK + k;
    *(__half2*)&g_Af[off + 0] = h01;
    *(__half2*)&g_Af[off + 2] = h23;
}

// ---------------------------------------------------------------------------
// Kernel 4: fp16 mma.sync GEMM (128x128xK512, single pass) + fused epilogue
//   4-stage cp.async pipeline, ONE __syncthreads per k-iteration
// ---------------------------------------------------------------------------
#define BK        32
#define ROWB      80                       // padded row bytes (40 halves)
#define SEC_B     (128 * ROWB)             // 10240 B per matrix section
#define STAGE_B   (2 * SEC_B)              // 20480 B
#define NSTG      4
#define KITERS    (KK / BK)                // 16
#define DYN_SMEM  (NSTG * STAGE_B)         // 81920 B

__global__ void __launch_bounds__(256, 2)
gemm_mma_kernel(float* __restrict__ hout, float* __restrict__ cout, int M) {
    extern __shared__ __align__(128) char sm[];
    __shared__ float s_bias[128];

    const int tid  = threadIdx.x;
    const int lane = tid & 31;
    const int wid  = tid >> 5;
    const int wm   = wid >> 2;            // 0..1  (64-row band)
    const int wn   = wid & 3;             // 0..3  (32-col band)
    const int m0   = blockIdx.y * 128;
    const int n0   = blockIdx.x * 128;
    const uint32_t smb = s2u(sm);

    if (tid < 128) s_bias[tid] = g_bias[n0 + tid];

    // ---- stage loader: 1024 x 16B cp.async ---------------------------------
    auto load_stage = [&](int s) {
        const uint32_t base = smb + (s & (NSTG - 1)) * STAGE_B;
        const int k0 = s * BK;
#pragma unroll
        for (int i = 0; i < 4; i++) {
            int l = tid + i * 256;
            int sec = l >> 9;             // 0=A 1=B
            int w = l & 511;
            int row = w >> 2;
            int ch = w & 3;
            const __half* src;
            if (sec == 0) {
                int gr = m0 + row; if (gr >= M) gr = M - 1;
                src = g_Af + (long long)gr * KK + k0 + ch * 8;
            } else {
                src = g_Bf + (long long)(n0 + row) * KK + k0 + ch * 8;
            }
            uint32_t dst = base + sec * SEC_B + row * ROWB + ch * 16;
            CPA16(dst, src);
        }
        CPA_COMMIT();
    };

    load_stage(0);
    load_stage(1);
    load_stage(2);

    float acc[4][4][4];
#pragma unroll
    for (int i = 0; i < 4; i++)
#pragma unroll
        for (int j = 0; j < 4; j++)
#pragma unroll
            for (int p = 0; p < 4; p++) acc[i][j][p] = 0.0f;

    const uint32_t aRow = (wm * 64 + (lane & 15)) * ROWB + (lane >> 4) * 16;
    const uint32_t bRow = (wn * 32 + (lane & 7) + ((lane >> 4) & 1) * 8) * ROWB
                          + ((lane >> 3) & 1) * 16;

#pragma unroll 4
    for (int s = 0; s < KITERS; s++) {
        // stage s ready when <= pending groups remain
        if (s <= KITERS - 3)      asm volatile("cp.async.wait_group 2;" ::: "memory");
        else if (s == KITERS - 2) asm volatile("cp.async.wait_group 1;" ::: "memory");
        else                      asm volatile("cp.async.wait_group 0;" ::: "memory");
        __syncthreads();
        // prefetch stage s+3 into buffer (s-1)%4 (all warps done with it)
        if (s + 3 < KITERS) load_stage(s + 3);

        const uint32_t base = smb + (s & (NSTG - 1)) * STAGE_B;
#pragma unroll
        for (int t = 0; t < 2; t++) {
            const uint32_t kb = t * 32;
            uint32_t ah[4][4], bh[2][4];
#pragma unroll
            for (int i = 0; i < 4; i++)
                ldsm4(ah[i], base + 0 * SEC_B + aRow + i * 16 * ROWB + kb);
#pragma unroll
            for (int j = 0; j < 2; j++)
                ldsm4(bh[j], base + 1 * SEC_B + bRow + j * 16 * ROWB + kb);
#pragma unroll
            for (int i = 0; i < 4; i++) {
#pragma unroll
                for (int jt = 0; jt < 4; jt++) {
                    mma16816(acc[i][jt], ah[i], &bh[jt >> 1][(jt & 1) * 2]);
                }
            }
        }
    }

    // ---- fused TreeLSTM epilogue ------------------------------------------
    // pair lanes (l, l^1) reassemble one full (i,o,u,f) quad via shfl.
    const int mbase = m0 + wm * 64;
    const int qbase = (n0 >> 2) + wn * 8;
    const int sub = (lane & 1);
#pragma unroll
    for (int i = 0; i < 4; i++) {
        const int mrow = mbase + i * 16 + (lane >> 2) + sub * 8;
        const bool valid = (mrow < M);
        const long long mb = (long long)mrow * HSZ;
#pragma unroll
        for (int j = 0; j < 4; j++) {
            float v0 = acc[i][j][0], v1 = acc[i][j][1];
            float v2 = acc[i][j][2], v3 = acc[i][j][3];
            float x0 = __shfl_xor_sync(0xFFFFFFFF, v0, 1);
            float x1 = __shfl_xor_sync(0xFFFFFFFF, v1, 1);
            float x2 = __shfl_xor_sync(0xFFFFFFFF, v2, 1);
            float x3 = __shfl_xor_sync(0xFFFFFFFF, v3, 1);
            float zi, zo, zu, zf;
            if (sub == 0) { zi = v0; zo = v1; zu = x0; zf = x1; }
            else          { zi = x2; zo = x3; zu = v2; zf = v3; }
            const int q = qbase + j * 2 + ((lane & 3) >> 1);
            const int ql = q - (n0 >> 2);
            float4 b4 = ((const float4*)s_bias)[ql];
            zi += b4.x; zo += b4.y; zu += b4.z; zf += b4.w;
            if (valid) {
                float cs = g_csum[mb + q];
                float cn = sig_(zi) * tanh_(zu) + sig_(zf) * cs;
                float hn = sig_(zo) * tanh_(cn);
                hout[mb + q] = hn;
                cout[mb + q] = cn;
            }
        }
    }
}

// ---------------------------------------------------------------------------
// launch
// ---------------------------------------------------------------------------
extern "C" void kernel_launch(void* const* d_in, const int* in_sizes, int n_in,
                              void* d_out, int out_size) {
    const float* x    = (const float*)d_in[0];
    const float* h    = (const float*)d_in[1];
    const float* c    = (const float*)d_in[2];
    const int*   src  = (const int*)d_in[3];
    const int*   dst  = (const int*)d_in[4];
    const float* Wiou = (const float*)d_in[5];
    const float* Uiou = (const float*)d_in[6];
    const float* biou = (const float*)d_in[7];
    const float* Ufw  = (const float*)d_in[8];
    const float* Ufb  = (const float*)d_in[9];

    const int E = in_sizes[3];
    const int M = in_sizes[0] / XSZ;

    float* hout = (float*)d_out;
    float* cout = (float*)d_out + (long long)M * HSZ;

    cudaFuncSetAttribute(gemm_mma_kernel,
                         cudaFuncAttributeMaxDynamicSharedMemorySize, DYN_SMEM);

    zero_kernel<<<4096, 256>>>();
    pack_kernel<<<(NOUT * KK + 255) / 256, 256>>>(Wiou, Uiou, biou, Ufw, Ufb);
    scatter_kernel<<<(E + 3) / 4, 256>>>(h, c, src, dst, E);
    convert_kernel<<<(int)(((long long)M * 128 + 255) / 256), 256>>>(x, M);

    dim3 grid(NOUT / 128, (M + 127) / 128);
    gemm_mma_kernel<<<grid, 256, DYN_SMEM>>>(hout, cout, M);
}

// round 9
// speedup vs baseline: 4.6713x; 1.1397x over previous
#include <cuda_runtime.h>
#include <cuda_fp16.h>
#include <math.h>
#include <stdint.h>

// Problem constants (fixed by the dataset)
#define NNODES 200000
#define HSZ    256
#define XSZ    256
#define KK     512          // packed K = XSZ + HSZ
#define NOUT   1024         // packed cols, interleaved gate quads (i,o,u,f)

// ---------------- device scratch (static allocation) ------------------------
__device__ float g_hsum[NNODES * HSZ];                 // 200 MB
__device__ float g_csum[NNODES * HSZ];                 // 200 MB
__device__ __half g_Af[(size_t)NNODES * KK];           // 204.8 MB  A = [x|hsum] fp16
__device__ __half g_Bf[NOUT * KK];                     // 1 MB  [n][k] K-major
__device__ float g_bias[NOUT];

// ---------------- PTX helpers (baseline compute_103 only) -------------------
__device__ __forceinline__ uint32_t s2u(const void* p) {
    uint32_t a;
    asm("{ .reg .u64 t; cvta.to.shared.u64 t, %1; cvt.u32.u64 %0, t; }"
        : "=r"(a) : "l"(p));
    return a;
}
#define CPA16(dst, src) \
    asm volatile("cp.async.cg.shared.global [%0], [%1], 16;" :: "r"(dst), "l"(src) : "memory")
#define CPA_COMMIT() asm volatile("cp.async.commit_group;" ::: "memory")

__device__ __forceinline__ void ldsm4(uint32_t* r, uint32_t addr) {
    asm volatile("ldmatrix.sync.aligned.m8n8.x4.shared.b16 {%0,%1,%2,%3}, [%4];"
                 : "=r"(r[0]), "=r"(r[1]), "=r"(r[2]), "=r"(r[3]) : "r"(addr));
}
__device__ __forceinline__ void mma16816(float* d, const uint32_t* a, const uint32_t* b) {
    asm volatile("mma.sync.aligned.m16n8k16.row.col.f32.f16.f16.f32 "
                 "{%0,%1,%2,%3}, {%4,%5,%6,%7}, {%8,%9}, {%0,%1,%2,%3};"
                 : "+f"(d[0]), "+f"(d[1]), "+f"(d[2]), "+f"(d[3])
                 : "r"(a[0]), "r"(a[1]), "r"(a[2]), "r"(a[3]), "r"(b[0]), "r"(b[1]));
}
// vectorized f32 reduction (PTX ISA 8.1+, sm_90+, not arch-'a' gated)
__device__ __forceinline__ void red_add_v4(float* p, float4 v) {
    asm volatile("red.add.v4.f32 [%0], {%1, %2, %3, %4};"
                 :: "l"(p), "f"(v.x), "f"(v.y), "f"(v.z), "f"(v.w) : "memory");
}

// fast sigmoid/tanh via ex2/rcp approx (rel err ~1e-6)
__device__ __forceinline__ float fexp2_(float x) {
    float y; asm("ex2.approx.ftz.f32 %0, %1;" : "=f"(y) : "f"(x)); return y;
}
__device__ __forceinline__ float frcp_(float x) {
    float y; asm("rcp.approx.ftz.f32 %0, %1;" : "=f"(y) : "f"(x)); return y;
}
__device__ __forceinline__ float sig_(float x) {
    return frcp_(1.0f + fexp2_(-1.4426950408889634f * x));
}
__device__ __forceinline__ float tanh_(float x) {
    return 2.0f * frcp_(1.0f + fexp2_(-2.8853900817779268f * x)) - 1.0f;
}

// ---------------------------------------------------------------------------
// Kernel 0: zero accumulators
// ---------------------------------------------------------------------------
__global__ void zero_kernel() {
    long long idx = (long long)blockIdx.x * blockDim.x + threadIdx.x;
    long long total4 = (long long)NNODES * HSZ / 4;
    float4 z = make_float4(0.f, 0.f, 0.f, 0.f);
    for (long long i = idx; i < total4; i += (long long)gridDim.x * blockDim.x) {
        ((float4*)g_hsum)[i] = z;
        ((float4*)g_csum)[i] = z;
    }
}

// ---------------------------------------------------------------------------
// Kernel 1: pack weights -> fp16, layout [n][k] K-major, n = 4q+t
// ---------------------------------------------------------------------------
__global__ void pack_kernel(const float* __restrict__ Wiou,
                            const float* __restrict__ Uiou,
                            const float* __restrict__ biou,
                            const float* __restrict__ Ufw,
                            const float* __restrict__ Ufb) {
    int idx = blockIdx.x * blockDim.x + threadIdx.x;
    if (idx < NOUT * KK) {
        int n = idx >> 9;
        int k = idx & (KK - 1);
        int q = n >> 2;
        int t = n & 3;
        float v;
        if (k < 256) {
            v = (t < 3) ? Wiou[(t * 256 + q) * XSZ + k] : 0.0f;
        } else {
            int kk = k - 256;
            v = (t < 3) ? Uiou[(t * 256 + q) * HSZ + kk] : Ufw[q * HSZ + kk];
        }
        g_Bf[idx] = __float2half_rn(v);
    }
    if (idx < NOUT) {
        int q = idx >> 2;
        int t = idx & 3;
        g_bias[idx] = (t < 3) ? biou[t * 256 + q] : Ufb[q];
    }
}

// ---------------------------------------------------------------------------
// Kernel 2: edge scatter-add with vectorized f32 reductions
// ---------------------------------------------------------------------------
__global__ void scatter_kernel(const float* __restrict__ h,
                               const float* __restrict__ c,
                               const int* __restrict__ src,
                               const int* __restrict__ dst,
                               int E) {
    int e = blockIdx.x * 4 + (threadIdx.x >> 6);
    if (e >= E) return;
    int lane = threadIdx.x & 63;
    int s = src[e];
    int d = dst[e];
    int off = lane * 4;
    float4 hv = *(const float4*)&h[(long long)s * HSZ + off];
    float4 cv = *(const float4*)&c[(long long)s * HSZ + off];
    red_add_v4(&g_hsum[(long long)d * HSZ + off], hv);
    red_add_v4(&g_csum[(long long)d * HSZ + off], cv);
}

// ---------------------------------------------------------------------------
// Kernel 3: convert A = [x | hsum] -> fp16 [m][512]
// ---------------------------------------------------------------------------
__global__ void convert_kernel(const float* __restrict__ x, int M) {
    long long i = (long long)blockIdx.x * blockDim.x + threadIdx.x;
    long long total = (long long)M * 128;          // one float4 each
    if (i >= total) return;
    int m = (int)(i >> 7);
    int k = ((int)i & 127) * 4;
    const float* sp = (k < 256) ? &x[(long long)m * 256 + k]
                                : &g_hsum[(long long)m * 256 + (k - 256)];
    float4 v = *(const float4*)sp;
    __half2 h01 = __floats2half2_rn(v.x, v.y);
    __half2 h23 = __floats2half2_rn(v.z, v.w);
    long long off = (long long)m * KK + k;
    *(__half2*)&g_Af[off + 0] = h01;
    *(__half2*)&g_Af[off + 2] = h23;
}

// ---------------------------------------------------------------------------
// Kernel 4: fp16 mma.sync GEMM (128x128xK512) + coalesced fused epilogue
//   4-stage cp.async pipeline, ONE __syncthreads per k-iteration;
//   epilogue: acc -> smem transpose -> 16-quad-per-thread coalesced I/O
// ---------------------------------------------------------------------------
#define BK        32
#define ROWB      80                       // padded row bytes (40 halves)
#define SEC_B     (128 * ROWB)             // 10240 B per matrix section
#define STAGE_B   (2 * SEC_B)              // 20480 B
#define NSTG      4
#define KITERS    (KK / BK)                // 16
#define DYN_SMEM  (NSTG * STAGE_B)         // 81920 B
#define SST       136                      // epilogue smem row stride (words)

__global__ void __launch_bounds__(256, 2)
gemm_mma_kernel(float* __restrict__ hout, float* __restrict__ cout, int M) {
    extern __shared__ __align__(128) char sm[];
    __shared__ __align__(16) float s_bias[128];   // 16B-aligned: read as float4

    const int tid  = threadIdx.x;
    const int lane = tid & 31;
    const int wid  = tid >> 5;
    const int wm   = wid >> 2;            // 0..1  (64-row band)
    const int wn   = wid & 3;             // 0..3  (32-col band)
    const int m0   = blockIdx.y * 128;
    const int n0   = blockIdx.x * 128;
    const uint32_t smb = s2u(sm);

    if (tid < 128) s_bias[tid] = g_bias[n0 + tid];

    // ---- stage loader: 1024 x 16B cp.async ---------------------------------
    auto load_stage = [&](int s) {
        const uint32_t base = smb + (s & (NSTG - 1)) * STAGE_B;
        const int k0 = s * BK;
#pragma unroll
        for (int i = 0; i < 4; i++) {
            int l = tid + i * 256;
            int sec = l >> 9;             // 0=A 1=B
            int w = l & 511;
            int row = w >> 2;
            int ch = w & 3;
            const __half* src;
            if (sec == 0) {
                int gr = m0 + row; if (gr >= M) gr = M - 1;
                src = g_Af + (long long)gr * KK + k0 + ch * 8;
            } else {
                src = g_Bf + (long long)(n0 + row) * KK + k0 + ch * 8;
            }
            uint32_t dst = base + sec * SEC_B + row * ROWB + ch * 16;
            CPA16(dst, src);
        }
        CPA_COMMIT();
    };

    load_stage(0);
    load_stage(1);
    load_stage(2);

    float acc[4][4][4];
#pragma unroll
    for (int i = 0; i < 4; i++)
#pragma unroll
        for (int j = 0; j < 4; j++)
#pragma unroll
            for (int p = 0; p < 4; p++) acc[i][j][p] = 0.0f;

    const uint32_t aRow = (wm * 64 + (lane & 15)) * ROWB + (lane >> 4) * 16;
    const uint32_t bRow = (wn * 32 + (lane & 7) + ((lane >> 4) & 1) * 8) * ROWB
                          + ((lane >> 3) & 1) * 16;

#pragma unroll 4
    for (int s = 0; s < KITERS; s++) {
        if (s <= KITERS - 3)      asm volatile("cp.async.wait_group 2;" ::: "memory");
        else if (s == KITERS - 2) asm volatile("cp.async.wait_group 1;" ::: "memory");
        else                      asm volatile("cp.async.wait_group 0;" ::: "memory");
        __syncthreads();
        if (s + 3 < KITERS) load_stage(s + 3);

        const uint32_t base = smb + (s & (NSTG - 1)) * STAGE_B;
#pragma unroll
        for (int t = 0; t < 2; t++) {
            const uint32_t kb = t * 32;
            uint32_t ah[4][4], bh[2][4];
#pragma unroll
            for (int i = 0; i < 4; i++)
                ldsm4(ah[i], base + 0 * SEC_B + aRow + i * 16 * ROWB + kb);
#pragma unroll
            for (int j = 0; j < 2; j++)
                ldsm4(bh[j], base + 1 * SEC_B + bRow + j * 16 * ROWB + kb);
#pragma unroll
            for (int i = 0; i < 4; i++) {
#pragma unroll
                for (int jt = 0; jt < 4; jt++) {
                    mma16816(acc[i][jt], ah[i], &bh[jt >> 1][(jt & 1) * 2]);
                }
            }
        }
    }

    // ---- epilogue phase 1: dump accumulators to smem ----------------------
    __syncthreads();            // all MMAs done; stage buffers reusable
    float* S = (float*)sm;      // [128][SST]
    {
        const int r0 = wm * 64 + (lane >> 2);
        const int c0 = wn * 32 + (lane & 3) * 2;
#pragma unroll
        for (int i = 0; i < 4; i++) {
#pragma unroll
            for (int jt = 0; jt < 4; jt++) {
                const int r = r0 + i * 16;
                const int c = c0 + jt * 8;
                *(float2*)&S[r * SST + c]       = make_float2(acc[i][jt][0], acc[i][jt][1]);
                *(float2*)&S[(r + 8) * SST + c] = make_float2(acc[i][jt][2], acc[i][jt][3]);
            }
        }
    }
    __syncthreads();

    // ---- epilogue phase 2: coalesced TreeLSTM -----------------------------
    // thread -> (row = tid>>1, half = tid&1): 16 consecutive quads
    {
        const int row  = tid >> 1;
        const int half = tid & 1;
        const int mrow = m0 + row;
        if (mrow < M) {
            const long long mb = (long long)mrow * HSZ;
            const int qg0 = (n0 >> 2) + half * 16;        // first global q
            const float* Srow = &S[row * SST + half * 64];
            const float4* bq = &((const float4*)s_bias)[half * 16];
            float4 csv[4];
#pragma unroll
            for (int v = 0; v < 4; v++)
                csv[v] = __ldcs((const float4*)&g_csum[mb + qg0 + v * 4]);
#pragma unroll
            for (int v = 0; v < 4; v++) {
                float hv[4], cv[4];
#pragma unroll
                for (int u = 0; u < 4; u++) {
                    const int qq = v * 4 + u;
                    float4 z = *(const float4*)&Srow[qq * 4];
                    float4 b = bq[qq];
                    float zi = z.x + b.x, zo = z.y + b.y;
                    float zu = z.z + b.z, zf = z.w + b.w;
                    float cs = (&csv[v].x)[u];
                    float cn = sig_(zi) * tanh_(zu) + sig_(zf) * cs;
                    cv[u] = cn;
                    hv[u] = sig_(zo) * tanh_(cn);
                }
                __stcs((float4*)&hout[mb + qg0 + v * 4],
                       make_float4(hv[0], hv[1], hv[2], hv[3]));
                __stcs((float4*)&cout[mb + qg0 + v * 4],
                       make_float4(cv[0], cv[1], cv[2], cv[3]));
            }
        }
    }
}

// ---------------------------------------------------------------------------
// launch
// ---------------------------------------------------------------------------
extern "C" void kernel_launch(void* const* d_in, const int* in_sizes, int n_in,
                              void* d_out, int out_size) {
    const float* x    = (const float*)d_in[0];
    const float* h    = (const float*)d_in[1];
    const float* c    = (const float*)d_in[2];
    const int*   src  = (const int*)d_in[3];
    const int*   dst  = (const int*)d_in[4];
    const float* Wiou = (const float*)d_in[5];
    const float* Uiou = (const float*)d_in[6];
    const float* biou = (const float*)d_in[7];
    const float* Ufw  = (const float*)d_in[8];
    const float* Ufb  = (const float*)d_in[9];

    const int E = in_sizes[3];
    const int M = in_sizes[0] / XSZ;

    float* hout = (float*)d_out;
    float* cout = (float*)d_out + (long long)M * HSZ;

    cudaFuncSetAttribute(gemm_mma_kernel,
                         cudaFuncAttributeMaxDynamicSharedMemorySize, DYN_SMEM);

    zero_kernel<<<4096, 256>>>();
    pack_kernel<<<(NOUT * KK + 255) / 256, 256>>>(Wiou, Uiou, biou, Ufw, Ufb);
    scatter_kernel<<<(E + 3) / 4, 256>>>(h, c, src, dst, E);
    convert_kernel<<<(int)(((long long)M * 128 + 255) / 256), 256>>>(x, M);

    dim3 grid(NOUT / 128, (M + 127) / 128);
    gemm_mma_kernel<<<grid, 256, DYN_SMEM>>>(hout, cout, M);
}